// round 10
// baseline (speedup 1.0000x reference)
#include <cuda_runtime.h>
#include <cuda_bf16.h>
#include <mma.h>
#include <cstdint>

using namespace nvcuda;

// Shapes (fixed by the reference)
#define B_   32
#define C_   512
#define N_   1024       // H*W
#define M_   77
#define MP_  128        // padded M
#define TD_  768
#define NH_  8
#define HD_  64
#define SCALE_ 0.125f   // 1/sqrt(64)

// Scratch (static __device__ — allocation-free per harness rules)
__device__ float g_Qt[B_ * C_ * N_];     // 64 MB  Qt[b][c][n]  (tf32-rounded)
__device__ float g_Kt[B_ * C_ * MP_];    //  8 MB  (tf32-rounded)
__device__ float g_Vt[B_ * C_ * MP_];    //  8 MB  (tf32-rounded)
__device__ float g_Wqr[C_ * C_];         //  1 MB  tf32-rounded operands
__device__ float g_Wkr[C_ * TD_];
__device__ float g_Wvr[C_ * TD_];
__device__ float g_xr[B_ * C_ * N_];     // 64 MB
__device__ float g_tr[B_ * M_ * TD_];    //  7.6 MB

// tf32 round-to-nearest
__device__ __forceinline__ float tf32r(float f) {
    uint32_t u;
    asm("cvt.rna.tf32.f32 %0, %1;" : "=r"(u) : "f"(f));
    return __uint_as_float(u);
}
__device__ __forceinline__ uint32_t smem_u32(const void* p) {
    uint32_t a;
    asm("{ .reg .u64 t; cvta.to.shared.u64 t, %1; cvt.u32.u64 %0, t; }"
        : "=r"(a) : "l"(p));
    return a;
}
__device__ __forceinline__ void cp16(uint32_t dst, const float* src) {
    asm volatile("cp.async.cg.shared.global [%0], [%1], 16;"
                 :: "r"(dst), "l"(src));
}
// zero-fill variant: src-size 0 -> 16 bytes of zeros, src not dereferenced
__device__ __forceinline__ void cp16z(uint32_t dst, const float* src, bool valid) {
    const int sz = valid ? 16 : 0;
    asm volatile("cp.async.cg.shared.global [%0], [%1], 16, %2;"
                 :: "r"(dst), "l"(src), "r"(sz));
}

// ---------------------------------------------------------------------------
// 0) Pre-round fp32 -> tf32 encodings (grid-stride, float4)
// ---------------------------------------------------------------------------
__global__ void round_kernel(const float* __restrict__ src, float* __restrict__ dst,
                             int n4) {
    for (int i = blockIdx.x * blockDim.x + threadIdx.x; i < n4;
         i += gridDim.x * blockDim.x) {
        float4 v = reinterpret_cast<const float4*>(src)[i];
        v.x = tf32r(v.x); v.y = tf32r(v.y); v.z = tf32r(v.z); v.w = tf32r(v.w);
        reinterpret_cast<float4*>(dst)[i] = v;
    }
}

// ===========================================================================
// tf32 WMMA GEMM: C[m][n] = A[m][k] @ B + bias[m]
//   block 128x128, 4 warps (2m x 2n), warp tile 64x64 = 4x4 wmma 16x16x8 frags
//   k-tile 32, double-buffered cp.async staging, 2 blocks/SM.
//   Operands are PRE-ROUNDED tf32 — no per-fragment convert loops.
//   Epilogue writes tf32-rounded C (consumed by tensor-core attention).
// ===========================================================================
#define A_LD   36
#define BQ_LD  132
#define BC_LD  36
#define A_FLOATS   (128 * A_LD)          // 4608
#define B_FLOATS   (128 * BC_LD)         // 4608 (>= 32*BQ_LD = 4224)
#define BUF_FLOATS (A_FLOATS + B_FLOATS) // 9216
#define GEMM_SMEM  (2 * BUF_FLOATS * 4)  // 73728 bytes

template<bool BCOL>
__device__ __forceinline__ void gemm_body(
    const float* __restrict__ A, const float* __restrict__ Bsrc,
    float* __restrict__ Cout, const float* __restrict__ bias,
    int K, int lda, int ldb, int ldc)
{
    extern __shared__ float smem[];
    const uint32_t smem_addr = smem_u32(smem);
    const int tid = threadIdx.x;          // 128 threads
    const int wid = tid >> 5, lane = tid & 31;
    const int wm = wid >> 1, wn = wid & 1;        // 2 x 2 warp grid
    const int rowBase = blockIdx.y << 7;
    const int colBase = blockIdx.x << 7;

    wmma::fragment<wmma::accumulator, 16, 16, 8, float> c[4][4];
#pragma unroll
    for (int i = 0; i < 4; i++)
#pragma unroll
        for (int j = 0; j < 4; j++) wmma::fill_fragment(c[i][j], 0.0f);

    auto stage = [&](int kt, int buf) {
        const uint32_t sA = smem_addr + buf * (BUF_FLOATS * 4);
        const uint32_t sB = sA + A_FLOATS * 4;
        const float* baseA = A + (size_t)rowBase * lda + kt * 32;
#pragma unroll
        for (int r4 = 0; r4 < 8; r4++) {            // A tile: [128][32]
            const int i4 = tid + (r4 << 7);
            const int row = i4 >> 3, c4 = (i4 & 7) << 2;
            cp16(sA + (uint32_t)(row * A_LD + c4) * 4, baseA + (size_t)row * lda + c4);
        }
        if (!BCOL) {                                 // B tile: [k=32][n=128]
            const float* baseB = Bsrc + (size_t)(kt * 32) * ldb + colBase;
#pragma unroll
            for (int r4 = 0; r4 < 8; r4++) {
                const int i4 = tid + (r4 << 7);
                const int k = i4 >> 5, n4 = (i4 & 31) << 2;
                cp16(sB + (uint32_t)(k * BQ_LD + n4) * 4, baseB + (size_t)k * ldb + n4);
            }
        } else {                                     // B tile: [n=128][k=32], pad n>=M_
            const float* baseB = Bsrc + kt * 32;
#pragma unroll
            for (int r4 = 0; r4 < 8; r4++) {
                const int i4 = tid + (r4 << 7);
                const int n = i4 >> 3, k4 = (i4 & 7) << 2;
                cp16z(sB + (uint32_t)(n * BC_LD + k4) * 4, baseB + (size_t)n * ldb + k4,
                      n < M_);
            }
        }
    };

    const int nkt = K >> 5;
    stage(0, 0);
    asm volatile("cp.async.commit_group;" ::: "memory");

    for (int kt = 0; kt < nkt; kt++) {
        const int buf = kt & 1;
        if (kt + 1 < nkt) {
            stage(kt + 1, buf ^ 1);
            asm volatile("cp.async.commit_group;" ::: "memory");
            asm volatile("cp.async.wait_group 1;" ::: "memory");
        } else {
            asm volatile("cp.async.wait_group 0;" ::: "memory");
        }
        __syncthreads();

        const float* As = smem + buf * BUF_FLOATS;
        const float* Bs = As + A_FLOATS;
#pragma unroll
        for (int ks = 0; ks < 4; ks++) {
            wmma::fragment<wmma::matrix_a, 16, 16, 8, wmma::precision::tf32,
                           wmma::row_major> a[4];
#pragma unroll
            for (int i = 0; i < 4; i++)
                wmma::load_matrix_sync(a[i], As + (wm * 64 + i * 16) * A_LD + ks * 8, A_LD);
#pragma unroll
            for (int j = 0; j < 4; j++) {
                if (!BCOL) {
                    wmma::fragment<wmma::matrix_b, 16, 16, 8, wmma::precision::tf32,
                                   wmma::row_major> b;
                    wmma::load_matrix_sync(b, Bs + ks * 8 * BQ_LD + (wn * 64 + j * 16),
                                           BQ_LD);
#pragma unroll
                    for (int i = 0; i < 4; i++) wmma::mma_sync(c[i][j], a[i], b, c[i][j]);
                } else {
                    wmma::fragment<wmma::matrix_b, 16, 16, 8, wmma::precision::tf32,
                                   wmma::col_major> b;
                    wmma::load_matrix_sync(b, Bs + (wn * 64 + j * 16) * BC_LD + ks * 8,
                                           BC_LD);
#pragma unroll
                    for (int i = 0; i < 4; i++) wmma::mma_sync(c[i][j], a[i], b, c[i][j]);
                }
            }
        }
        __syncthreads();   // staging buffers free for next prefetch / epilogue
    }

    // Epilogue: per-warp 16x16 smem patch, add bias, tf32-round, write C
    float* patch = smem + wid * 256;
#pragma unroll
    for (int i = 0; i < 4; i++) {
        const int row0 = rowBase + wm * 64 + i * 16;
#pragma unroll
        for (int j = 0; j < 4; j++) {
            const int col0 = colBase + wn * 64 + j * 16;
            wmma::store_matrix_sync(patch, c[i][j], 16, wmma::mem_row_major);
            __syncwarp();
#pragma unroll
            for (int e = lane; e < 256; e += 32) {
                const int r = e >> 4, cc = e & 15;
                Cout[(size_t)(row0 + r) * ldc + col0 + cc] =
                    tf32r(patch[e] + bias[row0 + r]);
            }
            __syncwarp();
        }
    }
}

// Qt[b] = Wq(512x512) @ x[b](512x1024) + bq   grid (8, 4, 32)
__global__ __launch_bounds__(128, 2)
void gemm_q_kernel(const float* __restrict__ bq) {
    const int b = blockIdx.z;
    gemm_body<false>(g_Wqr, g_xr + (size_t)b * C_ * N_, g_Qt + (size_t)b * C_ * N_,
                     bq, C_, C_, N_, N_);
}

// Kt/Vt[b] = W(512x768) @ text[b]^T + bias   grid (1, 4, 64), z = 2b+isV
__global__ __launch_bounds__(128, 2)
void gemm_kv_kernel(const float* __restrict__ bk, const float* __restrict__ bv) {
    const int z = blockIdx.z;
    const int b = z >> 1;
    const bool isV = (z & 1) != 0;
    gemm_body<true>(isV ? g_Wvr : g_Wkr, g_tr + (size_t)b * M_ * TD_,
                    (isV ? g_Vt : g_Kt) + (size_t)b * C_ * MP_,
                    isV ? bv : bk, TD_, TD_, TD_, MP_);
}

// ===========================================================================
// WMMA attention: block = (128-query tile, head, batch), 256 thr (8 warps).
//   Q/K/V arrive tf32-rounded — no convert loops. P rounded during softmax.
//   Phase 1: S[128][80] = Q·K^T (Qt col_major ld N_, Kt row_major ld MP_)
//   Softmax SIMT (one thread/row), p normalized+rounded in smem.
//   Phase 2: O = P·V, accumulators stored col_major DIRECTLY into out.
// ===========================================================================
#define S_LD 84   // 84 mod 32 = 20 -> 4-way LDS conflicts (ld 80 would be 16-way)

__global__ __launch_bounds__(256)
void attn_kernel(const int* __restrict__ mask, float* __restrict__ out) {
    __shared__ float Ssm[128 * S_LD];   // 43008 B
    __shared__ float msk[80];

    const int tid = threadIdx.x;
    const int wid = tid >> 5;
    const int b = blockIdx.z, h = blockIdx.y;
    const int n0 = blockIdx.x << 7;

    const float* Qbase = g_Qt + ((size_t)(b * C_ + h * HD_)) * N_ + n0; // (n,d)=ptr[d*N_+n]
    const float* Kbase = g_Kt + ((size_t)(b * C_ + h * HD_)) * MP_;     // (d,m)=ptr[d*MP_+m]
    const float* Vbase = g_Vt + ((size_t)(b * C_ + h * HD_)) * MP_;     // (m,d)=ptr[d*MP_+m]

    if (tid < 80)
        msk[tid] = (tid < M_ && mask[b * M_ + tid] != 0) ? 0.0f : -1e30f;

    // -------- Phase 1: S = Q @ K^T (warp w -> 16-row band, 5 col frags) ------
    {
        wmma::fragment<wmma::accumulator, 16, 16, 8, float> sacc[5];
#pragma unroll
        for (int j = 0; j < 5; j++) wmma::fill_fragment(sacc[j], 0.0f);
#pragma unroll
        for (int kf = 0; kf < 8; kf++) {      // d = kf*8
            wmma::fragment<wmma::matrix_a, 16, 16, 8, wmma::precision::tf32,
                           wmma::col_major> a;
            wmma::load_matrix_sync(a, Qbase + (size_t)(kf * 8) * N_ + wid * 16, N_);
#pragma unroll
            for (int j = 0; j < 5; j++) {
                wmma::fragment<wmma::matrix_b, 16, 16, 8, wmma::precision::tf32,
                               wmma::row_major> kb;
                wmma::load_matrix_sync(kb, Kbase + (size_t)(kf * 8) * MP_ + j * 16, MP_);
                wmma::mma_sync(sacc[j], a, kb, sacc[j]);
            }
        }
#pragma unroll
        for (int j = 0; j < 5; j++)
            wmma::store_matrix_sync(Ssm + (wid * 16) * S_LD + j * 16, sacc[j],
                                    S_LD, wmma::mem_row_major);
    }
    __syncthreads();

    // -------- Softmax: one thread per query row ------------------------------
    if (tid < 128) {
        float* row = Ssm + tid * S_LD;
        float mx = -1e30f;
#pragma unroll 7
        for (int m = 0; m < M_; m++) {
            const float s = row[m] * SCALE_ + msk[m];
            row[m] = s;
            mx = fmaxf(mx, s);
        }
        float sum = 0.0f;
#pragma unroll 7
        for (int m = 0; m < M_; m++) {
            const float p = __expf(row[m] - mx);
            row[m] = p;
            sum += p;
        }
        const float inv = 1.0f / sum;
#pragma unroll 7
        for (int m = 0; m < M_; m++) row[m] = tf32r(row[m] * inv);
        row[77] = 0.0f; row[78] = 0.0f; row[79] = 0.0f;   // kill padded keys
    }
    __syncthreads();

    // -------- Phase 2: O = P @ V (warp w -> 16-row band, 4 d-frags) ----------
    {
        wmma::fragment<wmma::accumulator, 16, 16, 8, float> oacc[4];
#pragma unroll
        for (int j = 0; j < 4; j++) wmma::fill_fragment(oacc[j], 0.0f);
#pragma unroll
        for (int kf = 0; kf < 10; kf++) {     // m = kf*8
            wmma::fragment<wmma::matrix_a, 16, 16, 8, wmma::precision::tf32,
                           wmma::row_major> a;
            wmma::load_matrix_sync(a, Ssm + (wid * 16) * S_LD + kf * 8, S_LD);
#pragma unroll
            for (int j = 0; j < 4; j++) {
                wmma::fragment<wmma::matrix_b, 16, 16, 8, wmma::precision::tf32,
                               wmma::col_major> vb;
                wmma::load_matrix_sync(vb, Vbase + (size_t)(j * 16) * MP_ + kf * 8, MP_);
                wmma::mma_sync(oacc[j], a, vb, oacc[j]);
            }
        }
        float* obase = out + ((size_t)(b * C_ + h * HD_)) * N_ + n0 + wid * 16;
#pragma unroll
        for (int j = 0; j < 4; j++)
            wmma::store_matrix_sync(obase + (size_t)(j * 16) * N_, oacc[j],
                                    N_, wmma::mem_col_major);
    }
}

// ---------------------------------------------------------------------------
// kernel_launch — inputs: 0:x 1:text_emb 2:attention_mask 3:Wq 4:bq 5:Wk 6:bk 7:Wv 8:bv
// ---------------------------------------------------------------------------
extern "C" void kernel_launch(void* const* d_in, const int* in_sizes, int n_in,
                              void* d_out, int out_size) {
    (void)in_sizes; (void)n_in; (void)out_size;
    const float* x    = (const float*)d_in[0];
    const float* text = (const float*)d_in[1];
    const int*   mask = (const int*)d_in[2];
    const float* Wq   = (const float*)d_in[3];
    const float* bq   = (const float*)d_in[4];
    const float* Wk   = (const float*)d_in[5];
    const float* bk   = (const float*)d_in[6];
    const float* Wv   = (const float*)d_in[7];
    const float* bv   = (const float*)d_in[8];
    float* out = (float*)d_out;

    cudaFuncSetAttribute(gemm_q_kernel,  cudaFuncAttributeMaxDynamicSharedMemorySize,
                         GEMM_SMEM);
    cudaFuncSetAttribute(gemm_kv_kernel, cudaFuncAttributeMaxDynamicSharedMemorySize,
                         GEMM_SMEM);

    float* wq_dst; float* wk_dst; float* wv_dst; float* x_dst; float* t_dst;
    cudaGetSymbolAddress((void**)&wq_dst, g_Wqr);
    cudaGetSymbolAddress((void**)&wk_dst, g_Wkr);
    cudaGetSymbolAddress((void**)&wv_dst, g_Wvr);
    cudaGetSymbolAddress((void**)&x_dst,  g_xr);
    cudaGetSymbolAddress((void**)&t_dst,  g_tr);

    round_kernel<<<256,  256>>>(Wq,   wq_dst, (C_ * C_) / 4);
    round_kernel<<<384,  256>>>(Wk,   wk_dst, (C_ * TD_) / 4);
    round_kernel<<<384,  256>>>(Wv,   wv_dst, (C_ * TD_) / 4);
    round_kernel<<<4096, 256>>>(x,    x_dst,  (B_ * C_ * N_) / 4);
    round_kernel<<<1024, 256>>>(text, t_dst,  (B_ * M_ * TD_) / 4);

    gemm_kv_kernel<<<dim3(1, 4, 64), 128, GEMM_SMEM>>>(bk, bv);
    gemm_q_kernel<<<dim3(8, 4, 32), 128, GEMM_SMEM>>>(bq);
    attn_kernel<<<dim3(8, 8, 32), 256>>>(mask, out);
}

// round 11
// speedup vs baseline: 1.1209x; 1.1209x over previous
#include <cuda_runtime.h>
#include <cuda_bf16.h>
#include <mma.h>
#include <cstdint>

using namespace nvcuda;

// Shapes (fixed by the reference)
#define B_   32
#define C_   512
#define N_   1024       // H*W
#define M_   77
#define MP_  128        // padded M
#define TD_  768
#define NH_  8
#define HD_  64
#define SCALE_ 0.125f   // 1/sqrt(64)

// Scratch (static __device__ — allocation-free per harness rules)
__device__ float g_Qt[B_ * C_ * N_];     // 64 MB  Qt[b][c][n]  (tf32-rounded)
__device__ float g_Kt[B_ * C_ * MP_];    //  8 MB  (tf32-rounded)
__device__ float g_Vt[B_ * C_ * MP_];    //  8 MB  (tf32-rounded)
__device__ float g_Wqr[C_ * C_];         //  1 MB  tf32-rounded operands
__device__ float g_Wkr[C_ * TD_];
__device__ float g_Wvr[C_ * TD_];
__device__ float g_tr[B_ * M_ * TD_];    //  7.6 MB

// tf32 round-to-nearest
__device__ __forceinline__ float tf32r(float f) {
    uint32_t u;
    asm("cvt.rna.tf32.f32 %0, %1;" : "=r"(u) : "f"(f));
    return __uint_as_float(u);
}
__device__ __forceinline__ uint32_t smem_u32(const void* p) {
    uint32_t a;
    asm("{ .reg .u64 t; cvta.to.shared.u64 t, %1; cvt.u32.u64 %0, t; }"
        : "=r"(a) : "l"(p));
    return a;
}
__device__ __forceinline__ void cp16(uint32_t dst, const float* src) {
    asm volatile("cp.async.cg.shared.global [%0], [%1], 16;"
                 :: "r"(dst), "l"(src));
}
// zero-fill variant: src-size 0 -> 16 bytes of zeros, src not dereferenced
__device__ __forceinline__ void cp16z(uint32_t dst, const float* src, bool valid) {
    const int sz = valid ? 16 : 0;
    asm volatile("cp.async.cg.shared.global [%0], [%1], 16, %2;"
                 :: "r"(dst), "l"(src), "r"(sz));
}

// ---------------------------------------------------------------------------
// 0) Pre-round fp32 -> tf32 encodings (weights + text only — cheap)
// ---------------------------------------------------------------------------
__global__ void round_kernel(const float* __restrict__ src, float* __restrict__ dst,
                             int n4) {
    for (int i = blockIdx.x * blockDim.x + threadIdx.x; i < n4;
         i += gridDim.x * blockDim.x) {
        float4 v = reinterpret_cast<const float4*>(src)[i];
        v.x = tf32r(v.x); v.y = tf32r(v.y); v.z = tf32r(v.z); v.w = tf32r(v.w);
        reinterpret_cast<float4*>(dst)[i] = v;
    }
}

// ===========================================================================
// tf32 WMMA GEMM: C[m][n] = A[m][k] @ B + bias[m]
//   block 128x128, 4 warps (2m x 2n), warp tile 64x64 = 4x4 wmma 16x16x8 frags
//   k-tile 32, double-buffered cp.async staging, 2 blocks/SM.
//   A is always pre-rounded tf32. BCVT: convert B fragments in-register
//   (used for the Q path where B = raw x; avoids a 128 MB round trip).
//   Epilogue writes tf32-rounded C (consumed by tensor-core attention).
// ===========================================================================
#define A_LD   36
#define BQ_LD  132
#define BC_LD  36
#define A_FLOATS   (128 * A_LD)          // 4608
#define B_FLOATS   (128 * BC_LD)         // 4608 (>= 32*BQ_LD = 4224)
#define BUF_FLOATS (A_FLOATS + B_FLOATS) // 9216
#define GEMM_SMEM  (2 * BUF_FLOATS * 4)  // 73728 bytes

template<bool BCOL, bool BCVT>
__device__ __forceinline__ void gemm_body(
    const float* __restrict__ A, const float* __restrict__ Bsrc,
    float* __restrict__ Cout, const float* __restrict__ bias,
    int K, int lda, int ldb, int ldc)
{
    extern __shared__ float smem[];
    const uint32_t smem_addr = smem_u32(smem);
    const int tid = threadIdx.x;          // 128 threads
    const int wid = tid >> 5, lane = tid & 31;
    const int wm = wid >> 1, wn = wid & 1;        // 2 x 2 warp grid
    const int rowBase = blockIdx.y << 7;
    const int colBase = blockIdx.x << 7;

    wmma::fragment<wmma::accumulator, 16, 16, 8, float> c[4][4];
#pragma unroll
    for (int i = 0; i < 4; i++)
#pragma unroll
        for (int j = 0; j < 4; j++) wmma::fill_fragment(c[i][j], 0.0f);

    auto stage = [&](int kt, int buf) {
        const uint32_t sA = smem_addr + buf * (BUF_FLOATS * 4);
        const uint32_t sB = sA + A_FLOATS * 4;
        const float* baseA = A + (size_t)rowBase * lda + kt * 32;
#pragma unroll
        for (int r4 = 0; r4 < 8; r4++) {            // A tile: [128][32]
            const int i4 = tid + (r4 << 7);
            const int row = i4 >> 3, c4 = (i4 & 7) << 2;
            cp16(sA + (uint32_t)(row * A_LD + c4) * 4, baseA + (size_t)row * lda + c4);
        }
        if (!BCOL) {                                 // B tile: [k=32][n=128]
            const float* baseB = Bsrc + (size_t)(kt * 32) * ldb + colBase;
#pragma unroll
            for (int r4 = 0; r4 < 8; r4++) {
                const int i4 = tid + (r4 << 7);
                const int k = i4 >> 5, n4 = (i4 & 31) << 2;
                cp16(sB + (uint32_t)(k * BQ_LD + n4) * 4, baseB + (size_t)k * ldb + n4);
            }
        } else {                                     // B tile: [n=128][k=32], pad n>=M_
            const float* baseB = Bsrc + kt * 32;
#pragma unroll
            for (int r4 = 0; r4 < 8; r4++) {
                const int i4 = tid + (r4 << 7);
                const int n = i4 >> 3, k4 = (i4 & 7) << 2;
                cp16z(sB + (uint32_t)(n * BC_LD + k4) * 4, baseB + (size_t)n * ldb + k4,
                      n < M_);
            }
        }
    };

    const int nkt = K >> 5;
    stage(0, 0);
    asm volatile("cp.async.commit_group;" ::: "memory");

    for (int kt = 0; kt < nkt; kt++) {
        const int buf = kt & 1;
        if (kt + 1 < nkt) {
            stage(kt + 1, buf ^ 1);
            asm volatile("cp.async.commit_group;" ::: "memory");
            asm volatile("cp.async.wait_group 1;" ::: "memory");
        } else {
            asm volatile("cp.async.wait_group 0;" ::: "memory");
        }
        __syncthreads();

        const float* As = smem + buf * BUF_FLOATS;
        const float* Bs = As + A_FLOATS;
#pragma unroll
        for (int ks = 0; ks < 4; ks++) {
            wmma::fragment<wmma::matrix_a, 16, 16, 8, wmma::precision::tf32,
                           wmma::row_major> a[4];
#pragma unroll
            for (int i = 0; i < 4; i++)
                wmma::load_matrix_sync(a[i], As + (wm * 64 + i * 16) * A_LD + ks * 8, A_LD);
#pragma unroll
            for (int j = 0; j < 4; j++) {
                if (!BCOL) {
                    wmma::fragment<wmma::matrix_b, 16, 16, 8, wmma::precision::tf32,
                                   wmma::row_major> b;
                    wmma::load_matrix_sync(b, Bs + ks * 8 * BQ_LD + (wn * 64 + j * 16),
                                           BQ_LD);
                    if (BCVT) {
#pragma unroll
                        for (int t = 0; t < b.num_elements; t++)
                            b.x[t] = wmma::__float_to_tf32(b.x[t]);
                    }
#pragma unroll
                    for (int i = 0; i < 4; i++) wmma::mma_sync(c[i][j], a[i], b, c[i][j]);
                } else {
                    wmma::fragment<wmma::matrix_b, 16, 16, 8, wmma::precision::tf32,
                                   wmma::col_major> b;
                    wmma::load_matrix_sync(b, Bs + (wn * 64 + j * 16) * BC_LD + ks * 8,
                                           BC_LD);
                    if (BCVT) {
#pragma unroll
                        for (int t = 0; t < b.num_elements; t++)
                            b.x[t] = wmma::__float_to_tf32(b.x[t]);
                    }
#pragma unroll
                    for (int i = 0; i < 4; i++) wmma::mma_sync(c[i][j], a[i], b, c[i][j]);
                }
            }
        }
        __syncthreads();   // staging buffers free for next prefetch / epilogue
    }

    // Epilogue: per-warp 16x16 smem patch, add bias, tf32-round, write C
    float* patch = smem + wid * 256;
#pragma unroll
    for (int i = 0; i < 4; i++) {
        const int row0 = rowBase + wm * 64 + i * 16;
#pragma unroll
        for (int j = 0; j < 4; j++) {
            const int col0 = colBase + wn * 64 + j * 16;
            wmma::store_matrix_sync(patch, c[i][j], 16, wmma::mem_row_major);
            __syncwarp();
#pragma unroll
            for (int e = lane; e < 256; e += 32) {
                const int r = e >> 4, cc = e & 15;
                Cout[(size_t)(row0 + r) * ldc + col0 + cc] =
                    tf32r(patch[e] + bias[row0 + r]);
            }
            __syncwarp();
        }
    }
}

// Qt[b] = Wq(512x512) @ x[b](512x1024) + bq   grid (8, 4, 32); B = raw x (cvt in reg)
__global__ __launch_bounds__(128, 2)
void gemm_q_kernel(const float* __restrict__ x, const float* __restrict__ bq) {
    const int b = blockIdx.z;
    gemm_body<false, true>(g_Wqr, x + (size_t)b * C_ * N_, g_Qt + (size_t)b * C_ * N_,
                           bq, C_, C_, N_, N_);
}

// Kt/Vt[b] = W(512x768) @ text[b]^T + bias   grid (1, 4, 64), z = 2b+isV
__global__ __launch_bounds__(128, 2)
void gemm_kv_kernel(const float* __restrict__ bk, const float* __restrict__ bv) {
    const int z = blockIdx.z;
    const int b = z >> 1;
    const bool isV = (z & 1) != 0;
    gemm_body<true, false>(isV ? g_Wvr : g_Wkr, g_tr + (size_t)b * M_ * TD_,
                           (isV ? g_Vt : g_Kt) + (size_t)b * C_ * MP_,
                           isV ? bv : bk, TD_, TD_, TD_, MP_);
}

// ===========================================================================
// WMMA attention v3: block = (256-query tile, head, batch), 256 thr (8 warps).
//   K and V staged ONCE into smem (kills the 8x-redundant strided global frag
//   loads of v2). Q frag loads stay global (each element read exactly once).
//   Phase 1: S[256][80] = Q·K^T; warp w -> 32-row band (2 row frags x 5 col).
//   Softmax SIMT one thread/row (scale+mask, normalize, tf32-round, pad-kill).
//   Phase 2: O = P·V, accumulators stored col_major DIRECTLY into out.
// ===========================================================================
#define S_LD  84
#define KV_LD 84
#define ATTN_SMEM_FLOATS (256 * S_LD + 2 * 64 * KV_LD + 80)
#define ATTN_SMEM_BYTES  (ATTN_SMEM_FLOATS * 4)    // 129344 B

__global__ __launch_bounds__(256)
void attn_kernel(const int* __restrict__ mask, float* __restrict__ out) {
    extern __shared__ float sm[];
    float* Ssm = sm;                         // [256][S_LD]
    float* Ks  = sm + 256 * S_LD;            // [64][KV_LD]  (d, m)
    float* Vs  = Ks + 64 * KV_LD;            // [64][KV_LD]  (d, m)
    float* msk = Vs + 64 * KV_LD;            // [80]

    const int tid = threadIdx.x;
    const int wid = tid >> 5;
    const int b = blockIdx.z, h = blockIdx.y;
    const int n0 = blockIdx.x << 8;          // 256-query tile

    const float* Qbase = g_Qt + ((size_t)(b * C_ + h * HD_)) * N_ + n0; // (n,d)=ptr[d*N_+n]
    const float* Kbase = g_Kt + ((size_t)(b * C_ + h * HD_)) * MP_;     // (d,m)=ptr[d*MP_+m]
    const float* Vbase = g_Vt + ((size_t)(b * C_ + h * HD_)) * MP_;

    // Stage K/V: 64 rows x 80 floats, coalesced float4 over m
    for (int i = tid; i < 64 * 20; i += 256) {
        const int d = i / 20, m4 = (i % 20) << 2;
        *reinterpret_cast<float4*>(&Ks[d * KV_LD + m4]) =
            *reinterpret_cast<const float4*>(Kbase + (size_t)d * MP_ + m4);
        *reinterpret_cast<float4*>(&Vs[d * KV_LD + m4]) =
            *reinterpret_cast<const float4*>(Vbase + (size_t)d * MP_ + m4);
    }
    if (tid < 80)
        msk[tid] = (tid < M_ && mask[b * M_ + tid] != 0) ? 0.0f : -1e30f;
    __syncthreads();

    // -------- Phase 1: S = Q @ K^T (warp w -> 32-row band) -------------------
    {
        wmma::fragment<wmma::accumulator, 16, 16, 8, float> sacc[2][5];
#pragma unroll
        for (int i = 0; i < 2; i++)
#pragma unroll
            for (int j = 0; j < 5; j++) wmma::fill_fragment(sacc[i][j], 0.0f);
#pragma unroll
        for (int kf = 0; kf < 8; kf++) {      // d = kf*8
            wmma::fragment<wmma::matrix_a, 16, 16, 8, wmma::precision::tf32,
                           wmma::col_major> a[2];
#pragma unroll
            for (int i = 0; i < 2; i++)
                wmma::load_matrix_sync(a[i],
                    Qbase + (size_t)(kf * 8) * N_ + wid * 32 + i * 16, N_);
#pragma unroll
            for (int j = 0; j < 5; j++) {
                wmma::fragment<wmma::matrix_b, 16, 16, 8, wmma::precision::tf32,
                               wmma::row_major> kb;
                wmma::load_matrix_sync(kb, Ks + (kf * 8) * KV_LD + j * 16, KV_LD);
#pragma unroll
                for (int i = 0; i < 2; i++) wmma::mma_sync(sacc[i][j], a[i], kb, sacc[i][j]);
            }
        }
#pragma unroll
        for (int i = 0; i < 2; i++)
#pragma unroll
            for (int j = 0; j < 5; j++)
                wmma::store_matrix_sync(Ssm + (wid * 32 + i * 16) * S_LD + j * 16,
                                        sacc[i][j], S_LD, wmma::mem_row_major);
    }
    __syncthreads();

    // -------- Softmax: one thread per query row ------------------------------
    {
        float* row = Ssm + tid * S_LD;
        float mx = -1e30f;
#pragma unroll 7
        for (int m = 0; m < M_; m++) {
            const float s = row[m] * SCALE_ + msk[m];
            row[m] = s;
            mx = fmaxf(mx, s);
        }
        float sum = 0.0f;
#pragma unroll 7
        for (int m = 0; m < M_; m++) {
            const float p = __expf(row[m] - mx);
            row[m] = p;
            sum += p;
        }
        const float inv = 1.0f / sum;
#pragma unroll 7
        for (int m = 0; m < M_; m++) row[m] = tf32r(row[m] * inv);
        row[77] = 0.0f; row[78] = 0.0f; row[79] = 0.0f;   // kill padded keys
    }
    __syncthreads();

    // -------- Phase 2: O = P @ V (warp w -> 32-row band, 4 d-frags) ----------
    {
        wmma::fragment<wmma::accumulator, 16, 16, 8, float> oacc[2][4];
#pragma unroll
        for (int i = 0; i < 2; i++)
#pragma unroll
            for (int j = 0; j < 4; j++) wmma::fill_fragment(oacc[i][j], 0.0f);
#pragma unroll
        for (int kf = 0; kf < 10; kf++) {     // m = kf*8
            wmma::fragment<wmma::matrix_a, 16, 16, 8, wmma::precision::tf32,
                           wmma::row_major> a[2];
#pragma unroll
            for (int i = 0; i < 2; i++)
                wmma::load_matrix_sync(a[i],
                    Ssm + (wid * 32 + i * 16) * S_LD + kf * 8, S_LD);
#pragma unroll
            for (int j = 0; j < 4; j++) {
                wmma::fragment<wmma::matrix_b, 16, 16, 8, wmma::precision::tf32,
                               wmma::col_major> vb;
                wmma::load_matrix_sync(vb, Vs + (j * 16) * KV_LD + kf * 8, KV_LD);
#pragma unroll
                for (int i = 0; i < 2; i++) wmma::mma_sync(oacc[i][j], a[i], vb, oacc[i][j]);
            }
        }
        float* obase = out + ((size_t)(b * C_ + h * HD_)) * N_ + n0 + wid * 32;
#pragma unroll
        for (int i = 0; i < 2; i++)
#pragma unroll
            for (int j = 0; j < 4; j++)
                wmma::store_matrix_sync(obase + i * 16 + (size_t)(j * 16) * N_,
                                        oacc[i][j], N_, wmma::mem_col_major);
    }
}

// ---------------------------------------------------------------------------
// kernel_launch — inputs: 0:x 1:text_emb 2:attention_mask 3:Wq 4:bq 5:Wk 6:bk 7:Wv 8:bv
// ---------------------------------------------------------------------------
extern "C" void kernel_launch(void* const* d_in, const int* in_sizes, int n_in,
                              void* d_out, int out_size) {
    (void)in_sizes; (void)n_in; (void)out_size;
    const float* x    = (const float*)d_in[0];
    const float* text = (const float*)d_in[1];
    const int*   mask = (const int*)d_in[2];
    const float* Wq   = (const float*)d_in[3];
    const float* bq   = (const float*)d_in[4];
    const float* Wk   = (const float*)d_in[5];
    const float* bk   = (const float*)d_in[6];
    const float* Wv   = (const float*)d_in[7];
    const float* bv   = (const float*)d_in[8];
    float* out = (float*)d_out;

    cudaFuncSetAttribute(gemm_q_kernel,  cudaFuncAttributeMaxDynamicSharedMemorySize,
                         GEMM_SMEM);
    cudaFuncSetAttribute(gemm_kv_kernel, cudaFuncAttributeMaxDynamicSharedMemorySize,
                         GEMM_SMEM);
    cudaFuncSetAttribute(attn_kernel, cudaFuncAttributeMaxDynamicSharedMemorySize,
                         ATTN_SMEM_BYTES);

    float* wq_dst; float* wk_dst; float* wv_dst; float* t_dst;
    cudaGetSymbolAddress((void**)&wq_dst, g_Wqr);
    cudaGetSymbolAddress((void**)&wk_dst, g_Wkr);
    cudaGetSymbolAddress((void**)&wv_dst, g_Wvr);
    cudaGetSymbolAddress((void**)&t_dst,  g_tr);

    round_kernel<<<256, 256>>>(Wq,   wq_dst, (C_ * C_) / 4);
    round_kernel<<<384, 256>>>(Wk,   wk_dst, (C_ * TD_) / 4);
    round_kernel<<<384, 256>>>(Wv,   wv_dst, (C_ * TD_) / 4);
    round_kernel<<<512, 256>>>(text, t_dst,  (B_ * M_ * TD_) / 4);

    gemm_kv_kernel<<<dim3(1, 4, 64), 128, GEMM_SMEM>>>(bk, bv);
    gemm_q_kernel<<<dim3(8, 4, 32), 128, GEMM_SMEM>>>(x, bq);
    attn_kernel<<<dim3(4, 8, 32), 256, ATTN_SMEM_BYTES>>>(mask, out);
}